// round 6
// baseline (speedup 1.0000x reference)
#include <cuda_runtime.h>
#include <cuda_bf16.h>
#include <cstdint>

// Problem shape
#define T_TOK   32
#define K_IN    4096
#define N_OUT   14336

// GEMM tiling
#define OTILE   128               // outputs per block
#define KC      64                // K ints per pipeline stage
#define NCHUNK  (K_IN / KC)       // 64
#define DEPTH   3                 // cp.async pipeline depth
#define TPB     256               // 8 warps
#define BSTRIDE 72                // padded SMEM row stride (ints) -> 288B, 16B aligned
#define STAGE_INTS (OTILE * BSTRIDE)          // 9216 ints = 36,864 B
#define SMEM_BYTES (DEPTH * STAGE_INTS * 4)   // 110,592 B

// A fragments, fragment-ready: [kstep s(256)][mtile(2)][half hi/lo(2)][lane(32)] -> 4 u32 regs
__device__ uint32_t g_afrag[256 * 2 * 2 * 32 * 4];    // 512 KB

// ---------------------------------------------------------------------------
// helpers
// ---------------------------------------------------------------------------
__device__ __forceinline__ float i2f_fast(int v) {   // exact for |v| < 2^22
    return __int_as_float(v + 0x4B400000) - 12582912.0f;
}

// pack two ints (already int8-valued) -> bf16x2 {lo=v0, hi=v1}
__device__ __forceinline__ uint32_t cvt2bf(int v0, int v1) {
    float f0 = i2f_fast(v0);
    float f1 = i2f_fast(v1);
    uint32_t r;
    asm("cvt.rn.bf16x2.f32 %0, %1, %2;" : "=r"(r) : "f"(f1), "f"(f0)); // first src -> high
    return r;
}

__device__ __forceinline__ void cp16(void* smem, const void* g) {
    uint32_t s = (uint32_t)__cvta_generic_to_shared(smem);
    asm volatile("cp.async.cg.shared.global [%0], [%1], 16;" :: "r"(s), "l"(g));
}

__device__ __forceinline__ void mma_bf16(float* d,
                                         uint32_t a0, uint32_t a1, uint32_t a2, uint32_t a3,
                                         uint32_t b0, uint32_t b1) {
    asm volatile(
        "mma.sync.aligned.m16n8k16.row.col.f32.bf16.bf16.f32 "
        "{%0,%1,%2,%3}, {%4,%5,%6,%7}, {%8,%9}, {%0,%1,%2,%3};"
        : "+f"(d[0]), "+f"(d[1]), "+f"(d[2]), "+f"(d[3])
        : "r"(a0), "r"(a1), "r"(a2), "r"(a3), "r"(b0), "r"(b1));
}

// ---------------------------------------------------------------------------
// Kernel 1: build fragment-ready A (hi/lo bf16 split of x*scales)
// one thread per (s, mt, lane, reg): computes the k-pair for both halves
// ---------------------------------------------------------------------------
__global__ void prep_kernel(const float* __restrict__ x,
                            const float* __restrict__ scales) {
    int tid = blockIdx.x * blockDim.x + threadIdx.x;    // 0 .. 65535
    int s    = tid >> 8;
    int rem  = tid & 255;
    int mt   = rem >> 7;
    int rem2 = rem & 127;
    int lane = rem2 >> 2;
    int reg  = rem2 & 3;

    int t = mt * 16 + (lane >> 2) + 8 * (reg & 1);           // token (m row)
    int k = s * 16 + ((lane & 3) * 2) + 8 * (reg >> 1);      // k (even)

    float xs0 = x[t * K_IN + k]     * scales[k];
    float xs1 = x[t * K_IN + k + 1] * scales[k + 1];

    __nv_bfloat16 h0 = __float2bfloat16(xs0);
    __nv_bfloat16 h1 = __float2bfloat16(xs1);
    __nv_bfloat16 l0 = __float2bfloat16(xs0 - __bfloat162float(h0));
    __nv_bfloat16 l1 = __float2bfloat16(xs1 - __bfloat162float(h1));

    uint32_t hp = ((uint32_t)__bfloat16_as_ushort(h1) << 16) | __bfloat16_as_ushort(h0);
    uint32_t lp = ((uint32_t)__bfloat16_as_ushort(l1) << 16) | __bfloat16_as_ushort(l0);

    int fhi = ((s * 2 + mt) * 2 + 0);
    int flo = ((s * 2 + mt) * 2 + 1);
    g_afrag[fhi * 128 + lane * 4 + reg] = hp;
    g_afrag[flo * 128 + lane * 4 + reg] = lp;
}

// ---------------------------------------------------------------------------
// Kernel 2: GEMM. block: 128 outputs x 32 tokens x full K (4096)
// 8 warps, each owns 16 outputs. cp.async 3-stage pipeline on weights.
// ---------------------------------------------------------------------------
__device__ __forceinline__ void load_stage(int* bs, const int* __restrict__ w,
                                           int o0, int k0, int tid) {
    #pragma unroll
    for (int j = 0; j < 8; j++) {
        int c   = j * 256 + tid;        // 0..2047 chunks of 16B
        int row = c >> 4;
        int kc  = c & 15;
        cp16(&bs[row * BSTRIDE + kc * 4],
             &w[(size_t)(o0 + row) * K_IN + k0 + kc * 4]);
    }
}

__global__ __launch_bounds__(TPB) void gemm_kernel(const int* __restrict__ w,
                                                   float* __restrict__ out) {
    extern __shared__ int bsm[];
    const int tid  = threadIdx.x;
    const int wid  = tid >> 5;
    const int lane = tid & 31;
    const int o0   = blockIdx.x * OTILE;

    float acc[2][2][4];
    #pragma unroll
    for (int a = 0; a < 2; a++)
        #pragma unroll
        for (int b = 0; b < 2; b++)
            #pragma unroll
            for (int r = 0; r < 4; r++) acc[a][b][r] = 0.f;

    // prologue: fill pipeline
    #pragma unroll
    for (int s = 0; s < DEPTH; s++) {
        load_stage(bsm + s * STAGE_INTS, w, o0, s * KC, tid);
        asm volatile("cp.async.commit_group;");
    }

    const uint4* __restrict__ afr = (const uint4*)g_afrag;
    const int aidx_lane = lane;   // lane offset within frag

    for (int c = 0; c < NCHUNK; c++) {
        asm volatile("cp.async.wait_group 2;");
        __syncthreads();

        const int* bs = bsm + (c % DEPTH) * STAGE_INTS;

        #pragma unroll
        for (int ks = 0; ks < 4; ks++) {
            int sglob = c * 4 + ks;
            // A fragments (hi/lo for both m-tiles): direct LDG.128, L1-broadcast
            uint4 Ah0 = afr[(((sglob * 2 + 0) * 2 + 0) * 32) + aidx_lane];
            uint4 Al0 = afr[(((sglob * 2 + 0) * 2 + 1) * 32) + aidx_lane];
            uint4 Ah1 = afr[(((sglob * 2 + 1) * 2 + 0) * 32) + aidx_lane];
            uint4 Al1 = afr[(((sglob * 2 + 1) * 2 + 1) * 32) + aidx_lane];

            #pragma unroll
            for (int nt = 0; nt < 2; nt++) {
                int orow = wid * 16 + nt * 8 + (lane >> 2);
                int kb   = ks * 16 + (lane & 3) * 2;
                int2 b01 = *reinterpret_cast<const int2*>(&bs[orow * BSTRIDE + kb]);
                int2 b23 = *reinterpret_cast<const int2*>(&bs[orow * BSTRIDE + kb + 8]);
                uint32_t B0 = cvt2bf(b01.x, b01.y);
                uint32_t B1 = cvt2bf(b23.x, b23.y);

                mma_bf16(acc[0][nt], Ah0.x, Ah0.y, Ah0.z, Ah0.w, B0, B1);
                mma_bf16(acc[0][nt], Al0.x, Al0.y, Al0.z, Al0.w, B0, B1);
                mma_bf16(acc[1][nt], Ah1.x, Ah1.y, Ah1.z, Ah1.w, B0, B1);
                mma_bf16(acc[1][nt], Al1.x, Al1.y, Al1.z, Al1.w, B0, B1);
            }
        }
        __syncthreads();

        if (c + DEPTH < NCHUNK)
            load_stage(bsm + ((c + DEPTH) % DEPTH) * STAGE_INTS, w, o0,
                       (c + DEPTH) * KC, tid);
        asm volatile("cp.async.commit_group;");   // empty group ok: keeps wait math simple
    }

    // epilogue: direct f32 stores
    #pragma unroll
    for (int mt = 0; mt < 2; mt++)
        #pragma unroll
        for (int nt = 0; nt < 2; nt++) {
            int t0 = mt * 16 + (lane >> 2);
            int o  = o0 + wid * 16 + nt * 8 + (lane & 3) * 2;
            float2 v0 = make_float2(acc[mt][nt][0], acc[mt][nt][1]);
            float2 v1 = make_float2(acc[mt][nt][2], acc[mt][nt][3]);
            *reinterpret_cast<float2*>(&out[(size_t)t0 * N_OUT + o])       = v0;
            *reinterpret_cast<float2*>(&out[(size_t)(t0 + 8) * N_OUT + o]) = v1;
        }
}

extern "C" void kernel_launch(void* const* d_in, const int* in_sizes, int n_in,
                              void* d_out, int out_size) {
    const float* x      = (const float*)d_in[0];
    const int*   weight = (const int*)d_in[1];
    const float* scales = (const float*)d_in[2];
    float* out = (float*)d_out;

    static bool attr_done = false;
    if (!attr_done) {
        cudaFuncSetAttribute(gemm_kernel,
                             cudaFuncAttributeMaxDynamicSharedMemorySize, SMEM_BYTES);
        attr_done = true;
    }

    prep_kernel<<<128, 512>>>(x, scales);
    gemm_kernel<<<N_OUT / OTILE, TPB, SMEM_BYTES>>>(weight, out);
}

// round 10
// speedup vs baseline: 2.1364x; 2.1364x over previous
#include <cuda_runtime.h>
#include <cuda_bf16.h>
#include <cstdint>

// Problem shape
#define T_TOK   32
#define K_IN    4096
#define N_OUT   14336

// GEMM tiling: no smem, register-direct B stream
#define OTILE   64                // outputs per block (8 warps x 8 outputs)
#define TPB     256
#define NKSTEP  (K_IN / 16)       // 256 mma k-steps
#define NCHUNK  (NKSTEP / 4)      // 64 (unroll 4 k-steps)

// A fragments, fragment-ready: [kstep s(256)][mtile(2)][half hi/lo(2)] -> 32 lanes x 4 regs
__device__ uint32_t g_afrag[256 * 2 * 2 * 32 * 4];    // 512 KB

// ---------------------------------------------------------------------------
// helpers
// ---------------------------------------------------------------------------
__device__ __forceinline__ float i2f_fast(int v) {   // exact for |v| < 2^22
    return __int_as_float(v + 0x4B400000) - 12582912.0f;
}

// pack two ints (int8-valued) -> bf16x2 {lo=v0, hi=v1}
__device__ __forceinline__ uint32_t cvt2bf(int v0, int v1) {
    float f0 = i2f_fast(v0);
    float f1 = i2f_fast(v1);
    uint32_t r;
    asm("cvt.rn.bf16x2.f32 %0, %1, %2;" : "=r"(r) : "f"(f1), "f"(f0)); // first src -> high
    return r;
}

__device__ __forceinline__ void mma_bf16(float* d, const uint4& a,
                                         uint32_t b0, uint32_t b1) {
    asm volatile(
        "mma.sync.aligned.m16n8k16.row.col.f32.bf16.bf16.f32 "
        "{%0,%1,%2,%3}, {%4,%5,%6,%7}, {%8,%9}, {%0,%1,%2,%3};"
        : "+f"(d[0]), "+f"(d[1]), "+f"(d[2]), "+f"(d[3])
        : "r"(a.x), "r"(a.y), "r"(a.z), "r"(a.w), "r"(b0), "r"(b1));
}

// ---------------------------------------------------------------------------
// Kernel 1: build fragment-ready A (hi/lo bf16 split of x*scales)
// coalesced: consecutive threads -> consecutive k-pairs of one token row
// ---------------------------------------------------------------------------
__global__ void prep_kernel(const float* __restrict__ x,
                            const float* __restrict__ scales) {
    int gtid = blockIdx.x * blockDim.x + threadIdx.x;   // 0 .. 65535
    int t  = gtid >> 11;          // token 0..31
    int kp = gtid & 2047;         // k-pair 0..2047

    float2 xv = *reinterpret_cast<const float2*>(&x[t * K_IN + kp * 2]);
    float2 sv = *reinterpret_cast<const float2*>(&scales[kp * 2]);
    float xs0 = xv.x * sv.x;
    float xs1 = xv.y * sv.y;

    __nv_bfloat16 h0 = __float2bfloat16(xs0);
    __nv_bfloat16 h1 = __float2bfloat16(xs1);
    __nv_bfloat16 l0 = __float2bfloat16(xs0 - __bfloat162float(h0));
    __nv_bfloat16 l1 = __float2bfloat16(xs1 - __bfloat162float(h1));

    uint32_t hp = ((uint32_t)__bfloat16_as_ushort(h1) << 16) | __bfloat16_as_ushort(h0);
    uint32_t lp = ((uint32_t)__bfloat16_as_ushort(l1) << 16) | __bfloat16_as_ushort(l0);

    // fragment coordinates for (t, k=2*kp)
    int s    = kp >> 3;                               // k-step
    int mt   = t >> 4;
    int lane = (t & 7) * 4 + (kp & 3);
    int reg  = ((t >> 3) & 1) | (((kp >> 2) & 1) << 1);

    int fhi = s * 4 + mt * 2 + 0;
    int flo = s * 4 + mt * 2 + 1;
    g_afrag[fhi * 128 + lane * 4 + reg] = hp;
    g_afrag[flo * 128 + lane * 4 + reg] = lp;
}

// ---------------------------------------------------------------------------
// Kernel 2: GEMM, smem-free. 8 warps/CTA, each warp: 8 outputs x 32 tokens x full K.
// B streamed LDG->reg, A fragments broadcast-read from g_afrag (L1/L2).
// ---------------------------------------------------------------------------
__global__ __launch_bounds__(TPB, 2) void gemm_kernel(const int* __restrict__ w,
                                                      float* __restrict__ out) {
    const int tid  = threadIdx.x;
    const int wid  = tid >> 5;
    const int lane = tid & 31;
    const int o0   = blockIdx.x * OTILE;
    const int orow = o0 + wid * 8 + (lane >> 2);      // this thread's B row

    const int* __restrict__ wbase = w + (size_t)orow * K_IN + (lane & 3) * 2;
    const uint4* __restrict__ afr = (const uint4*)g_afrag + lane;

    float acc[2][4];
    #pragma unroll
    for (int m = 0; m < 2; m++)
        #pragma unroll
        for (int r = 0; r < 4; r++) acc[m][r] = 0.f;

    for (int c = 0; c < NCHUNK; c++) {
        const int k0 = c * 64;

        // front-batched B loads for 4 k-steps: 8 x LDG.64 outstanding
        int2 b[8];
        #pragma unroll
        for (int ks = 0; ks < 4; ks++) {
            b[2 * ks]     = __ldg((const int2*)(wbase + k0 + ks * 16));
            b[2 * ks + 1] = __ldg((const int2*)(wbase + k0 + ks * 16 + 8));
        }

        #pragma unroll
        for (int ks = 0; ks < 4; ks++) {
            const int sg = (c * 4 + ks) * 4;
            const uint4 Ah0 = afr[(sg + 0) * 32];
            const uint4 Al0 = afr[(sg + 1) * 32];
            const uint4 Ah1 = afr[(sg + 2) * 32];
            const uint4 Al1 = afr[(sg + 3) * 32];

            const uint32_t B0 = cvt2bf(b[2 * ks].x, b[2 * ks].y);
            const uint32_t B1 = cvt2bf(b[2 * ks + 1].x, b[2 * ks + 1].y);

            mma_bf16(acc[0], Ah0, B0, B1);
            mma_bf16(acc[0], Al0, B0, B1);
            mma_bf16(acc[1], Ah1, B0, B1);
            mma_bf16(acc[1], Al1, B0, B1);
        }
    }

    // epilogue: direct f32 stores (C frag: rows lane>>2 and +8, cols (lane&3)*2..+1)
    const int ocol = o0 + wid * 8 + (lane & 3) * 2;
    #pragma unroll
    for (int mt = 0; mt < 2; mt++) {
        int t0 = mt * 16 + (lane >> 2);
        *reinterpret_cast<float2*>(&out[(size_t)t0 * N_OUT + ocol]) =
            make_float2(acc[mt][0], acc[mt][1]);
        *reinterpret_cast<float2*>(&out[(size_t)(t0 + 8) * N_OUT + ocol]) =
            make_float2(acc[mt][2], acc[mt][3]);
    }
}

extern "C" void kernel_launch(void* const* d_in, const int* in_sizes, int n_in,
                              void* d_out, int out_size) {
    const float* x      = (const float*)d_in[0];
    const int*   weight = (const int*)d_in[1];
    const float* scales = (const float*)d_in[2];
    float* out = (float*)d_out;

    prep_kernel<<<128, 512>>>(x, scales);
    gemm_kernel<<<N_OUT / OTILE, TPB>>>(weight, out);
}